// round 16
// baseline (speedup 1.0000x reference)
#include <cuda_runtime.h>
#include <cuda_fp16.h>
#include <cstdint>

#define N_NODES_MAX 100000
#define N_EDGES_MAX 600000

// ---------------------------------------------------------------------------
// Scratch (device globals)
// ---------------------------------------------------------------------------
__device__ __align__(16) __half g_eaggh[(size_t)N_NODES_MAX * 32];   // mean edge_attr (half)
__device__ __align__(16) __half g_xh   [(size_t)N_NODES_MAX * 128];  // half(x)
__device__ __align__(16) __half g_h1h  [(size_t)N_NODES_MAX * 128];  // layer-1 out (half)
__device__ __align__(16) __half g_h2h  [(size_t)N_NODES_MAX * 128];  // layer-2 out (half)
__device__ __align__(16) float  g_af   [(size_t)N_NODES_MAX * 128];  // predictor 'a' (fp32)
__device__ __align__(16) float  g_bf   [(size_t)N_NODES_MAX * 128];  // predictor 'b' (fp32)
__device__ __align__(16) float  g_degc [N_NODES_MAX];                // deg>0 ? 1 : 0
__device__ __align__(16) __half g_Wcath[2 * 128 * 288];              // [n][Wl^T|P^T|Wr^T]
__device__ __align__(16) __half g_Wpth [2 * 128 * 128];              // Wp1a^T, Wp1b^T
__device__ __align__(16) float  g_bv1  [2 * 128];                    // be_l @ Wl_l
__device__ __align__(16) float  g_bv0  [2 * 128];                    // bl_l + br_l
// CSR
__device__ int g_rowptr[N_NODES_MAX + 1];
__device__ int g_cnt   [N_NODES_MAX];
__device__ int g_bsum  [1024];
__device__ int g_boff  [1024];
__device__ int g_csr_src[N_EDGES_MAX];
__device__ int g_csr_eid[N_EDGES_MAX];

// ---------------------------------------------------------------------------
// helpers
// ---------------------------------------------------------------------------
__device__ __forceinline__ void cp16(uint32_t dst, const void* src, int srcsize) {
    asm volatile("cp.async.ca.shared.global [%0], [%1], 16, %2;"
                 :: "r"(dst), "l"(src), "r"(srcsize) : "memory");
}
__device__ __forceinline__ void cp_commit() {
    asm volatile("cp.async.commit_group;" ::: "memory");
}
template <int N>
__device__ __forceinline__ void cp_wait() {
    asm volatile("cp.async.wait_group %0;" :: "n"(N) : "memory");
}
__device__ __forceinline__ void mma_f16(float c[4], const uint32_t a[4],
                                        uint32_t b0, uint32_t b1) {
    asm("mma.sync.aligned.m16n8k16.row.col.f32.f16.f16.f32 "
        "{%0,%1,%2,%3}, {%4,%5,%6,%7}, {%8,%9}, {%0,%1,%2,%3};"
        : "+f"(c[0]), "+f"(c[1]), "+f"(c[2]), "+f"(c[3])
        : "r"(a[0]), "r"(a[1]), "r"(a[2]), "r"(a[3]), "r"(b0), "r"(b1));
}

// ---------------------------------------------------------------------------
// CSR build
// ---------------------------------------------------------------------------
__global__ void k_hist(const int* __restrict__ ei, int* __restrict__ cnt, int E, int N) {
    int e = blockIdx.x * blockDim.x + threadIdx.x;
    if (e < E) {
        int d = ei[E + e];
        if ((unsigned)d < (unsigned)N) atomicAdd(&cnt[d], 1);
    }
}
__global__ void k_scan1(const int* __restrict__ cnt, int* __restrict__ rowptr,
                        int* __restrict__ bsum, int N) {
    __shared__ int sm[512];
    int t = threadIdx.x, b = blockIdx.x, i = b * 512 + t;
    int v = (i < N) ? cnt[i] : 0;
    sm[t] = v;
    __syncthreads();
    #pragma unroll
    for (int off = 1; off < 512; off <<= 1) {
        int add = (t >= off) ? sm[t - off] : 0;
        __syncthreads();
        sm[t] += add;
        __syncthreads();
    }
    if (i < N) rowptr[i + 1] = sm[t];
    if (t == 511) bsum[b] = sm[511];
}
__global__ void k_scan2(const int* __restrict__ bsum, int* __restrict__ boff, int nb) {
    __shared__ int sm[1024];
    int t = threadIdx.x;
    sm[t] = (t < nb) ? bsum[t] : 0;
    __syncthreads();
    #pragma unroll
    for (int off = 1; off < 1024; off <<= 1) {
        int add = (t >= off) ? sm[t - off] : 0;
        __syncthreads();
        sm[t] += add;
        __syncthreads();
    }
    if (t < nb) boff[t] = (t == 0) ? 0 : sm[t - 1];
}
__global__ void k_scan3(int* __restrict__ rowptr, const int* __restrict__ boff,
                        int* __restrict__ cnt, float* __restrict__ degc, int N) {
    int t = threadIdx.x, b = blockIdx.x, i = b * 512 + t;
    if (i < N) {
        rowptr[i + 1] += boff[b];
        degc[i] = cnt[i] > 0 ? 1.f : 0.f;
        cnt[i] = 0;
        if (i == 0) rowptr[0] = 0;
    }
}
__global__ void k_fill(const int* __restrict__ ei, const int* __restrict__ rowptr,
                       int* __restrict__ cnt, int* __restrict__ csr_src,
                       int* __restrict__ csr_eid, int E, int N) {
    int e = blockIdx.x * blockDim.x + threadIdx.x;
    if (e < E) {
        int s = ei[e];
        int d = ei[E + e];
        if ((unsigned)d < (unsigned)N) {
            int pos = rowptr[d] + atomicAdd(&cnt[d], 1);
            csr_src[pos] = s;
            csr_eid[pos] = e;
        }
    }
}

// ---------------------------------------------------------------------------
// x -> half copy
// ---------------------------------------------------------------------------
__global__ void k_xhalf(const float4* __restrict__ x, uint2* __restrict__ xh, int n4) {
    int i = blockIdx.x * blockDim.x + threadIdx.x;
    int stride = gridDim.x * blockDim.x;
    for (; i < n4; i += stride) {
        float4 v = x[i];
        __half2 p0 = __floats2half2_rn(v.x, v.y);
        __half2 p1 = __floats2half2_rn(v.z, v.w);
        uint2 u;
        u.x = *(uint32_t*)&p0;
        u.y = *(uint32_t*)&p1;
        xh[i] = u;
    }
}

// ---------------------------------------------------------------------------
// Weight prep (half, transposed K-major)
// ---------------------------------------------------------------------------
__global__ void k_wprep(const float* We1, const float* be1, const float* Wl1,
                        const float* bl1, const float* br1, const float* Wr1,
                        const float* We2, const float* be2, const float* Wl2,
                        const float* bl2, const float* br2, const float* Wr2,
                        const float* Wp1,
                        __half* Wcat, __half* Wpt, float* bv1, float* bv0) {
    int l = blockIdx.x;
    int j = threadIdx.x;
    if (l < 2) {
        const float* We = l ? We2 : We1;
        const float* be = l ? be2 : be1;
        const float* Wl = l ? Wl2 : Wl1;
        const float* bl = l ? bl2 : bl1;
        const float* br = l ? br2 : br1;
        const float* Wr = l ? Wr2 : Wr1;
        __half* row = Wcat + (size_t)l * 128 * 288 + (size_t)j * 288;
        for (int k = 0; k < 128; k++) row[k] = __float2half_rn(Wl[k * 128 + j]);
        for (int i = 0; i < 32; i++) {
            float acc = 0.f;
            for (int k = 0; k < 128; k++) acc = fmaf(We[i * 128 + k], Wl[k * 128 + j], acc);
            row[128 + i] = __float2half_rn(acc);
        }
        for (int k = 0; k < 128; k++) row[160 + k] = __float2half_rn(Wr[k * 128 + j]);
        float a1 = 0.f;
        for (int k = 0; k < 128; k++) a1 = fmaf(be[k], Wl[k * 128 + j], a1);
        bv1[l * 128 + j] = a1;
        bv0[l * 128 + j] = bl[j] + br[j];
    } else {
        __half* ra = Wpt + (size_t)j * 128;
        __half* rb = Wpt + (size_t)128 * 128 + (size_t)j * 128;
        for (int k = 0; k < 128; k++) {
            ra[k] = __float2half_rn(Wp1[k * 128 + j]);
            rb[k] = __float2half_rn(Wp1[(128 + k) * 128 + j]);
        }
    }
}

// ---------------------------------------------------------------------------
// FUSED SAGE layer: CSR aggregation (phase 1, warp-per-row into smem) +
// fp16 tensor-core GEMM (phase 2) in one kernel.
//   h_out = relu( mean @ Wl^T + eagg_mean @ P^T + xsrc @ Wr^T + bv0 + degc*bv1 )
// smem (u32 words): aggA[128][68] | eaggS[128][20] | 3 stages x (W[128][20] + Ax[128][20])
// aggA row = 64 data words (128 halves) + 4 pad; frag banks (4g+q)%32 distinct.
// K-tiles t=0..8: t<4 A=aggA (persistent) | t==4 A=eaggS | t>4 A=Ax stream (xsrc)
// ---------------------------------------------------------------------------
#define SAGE_SMEM ((128 * 68 + 128 * 20 + 3 * 2 * 128 * 20) * 4)   // 106496 B

__global__ __launch_bounds__(256)
void k_sage(const __half* __restrict__ xsrc,      // gather + stream source
            const float* __restrict__ ea,          // layer1 only, else null
            const int* __restrict__ rowptr,
            const int* __restrict__ csr_src,
            const int* __restrict__ csr_eid,
            const __half* __restrict__ Wt,         // [128][288] K-major
            __half* __restrict__ eaggh,            // global eagg (write l1 / read l2)
            const float* __restrict__ bv0,
            const float* __restrict__ bv1,
            const float* __restrict__ degc,
            __half* __restrict__ Ch,
            int Nn) {
    extern __shared__ __align__(16) uint32_t smem[];
    uint32_t* aggA  = smem;                 // [128][68]
    uint32_t* eaggS = smem + 8704;          // [128][20]
    auto wS  = [&](int s) { return smem + 11264 + s * 5120; };        // [128][20]
    auto axS = [&](int s) { return smem + 11264 + s * 5120 + 2560; }; // [128][20]

    const int tid    = threadIdx.x;
    const int lane   = tid & 31;
    const int warp   = tid >> 5;
    const int gid    = lane >> 2;
    const int qid    = lane & 3;
    const int warp_m = warp >> 1;
    const int warp_n = warp & 1;
    const int m0     = blockIdx.x * 128;

    // issue W tile t (and Ax stream tile for t>=5) into stage s
    auto issue_tile = [&](int t, int s) {
        uint32_t wbase = (uint32_t)__cvta_generic_to_shared(wS(s));
        const int bkb = t * 32;
        #pragma unroll
        for (int i = 0; i < 2; i++) {
            int chunk = tid + i * 256;
            int r = chunk >> 2, qc = chunk & 3;
            cp16(wbase + (r * 20 + qc * 4) * 4, Wt + (size_t)r * 288 + bkb + qc * 8, 16);
        }
        if (t >= 5) {
            uint32_t abase = (uint32_t)__cvta_generic_to_shared(axS(s));
            const int akb = (t - 5) * 32;
            #pragma unroll
            for (int i = 0; i < 2; i++) {
                int chunk = tid + i * 256;
                int r = chunk >> 2, qc = chunk & 3;
                int gm = m0 + r;
                cp16(abase + (r * 20 + qc * 4) * 4,
                     xsrc + (size_t)gm * 128 + akb + qc * 8, gm < Nn ? 16 : 0);
            }
        }
        cp_commit();
    };

    // prefetch first two W tiles — they land while we aggregate
    issue_tile(0, 0);
    issue_tile(1, 1);

    // ---------------- phase 1: aggregation (warp per row) ----------------
    const uint2* x2 = (const uint2*)xsrc;
    for (int i = 0; i < 16; i++) {
        int row = warp + 8 * i;           // 0..127
        int n = m0 + row;
        float4 acc = make_float4(0.f, 0.f, 0.f, 0.f);
        float eacc = 0.f;
        float inv = 1.f;
        if (n < Nn) {
            int beg = rowptr[n], end = rowptr[n + 1];
            inv = 1.f / fmaxf((float)(end - beg), 1.f);
            for (int e = beg; e < end; e++) {
                int s0 = __ldg(&csr_src[e]);
                uint2 u = __ldg(x2 + (size_t)s0 * 32 + lane);
                float2 f0 = __half22float2(*(__half2*)&u.x);
                float2 f1 = __half22float2(*(__half2*)&u.y);
                acc.x += f0.x; acc.y += f0.y; acc.z += f1.x; acc.w += f1.y;
                if (ea) {
                    int e0 = __ldg(&csr_eid[e]);
                    eacc += __ldg(&ea[(size_t)e0 * 32 + lane]);
                }
            }
        }
        __half2 p0 = __floats2half2_rn(acc.x * inv, acc.y * inv);
        __half2 p1 = __floats2half2_rn(acc.z * inv, acc.w * inv);
        aggA[row * 68 + 2 * lane]     = *(uint32_t*)&p0;
        aggA[row * 68 + 2 * lane + 1] = *(uint32_t*)&p1;
        if (ea) {
            float eh = eacc * inv;
            if (n < Nn) eaggh[(size_t)n * 32 + lane] = __float2half_rn(eh);
            float ep = __shfl_xor_sync(0xffffffffu, eh, 1);
            if (!(lane & 1)) {
                __half2 hp = __floats2half2_rn(eh, ep);
                eaggS[row * 20 + (lane >> 1)] = *(uint32_t*)&hp;
            }
        }
    }
    if (!ea) {
        // layer 2: eagg tile from global
        #pragma unroll
        for (int i = 0; i < 2; i++) {
            int chunk = tid + i * 256;
            int r = chunk >> 2, qc = chunk & 3;
            int gm = m0 + r;
            uint4 v = make_uint4(0u, 0u, 0u, 0u);
            if (gm < Nn) v = *(const uint4*)(eaggh + (size_t)gm * 32 + qc * 8);
            *(uint4*)&eaggS[r * 20 + qc * 4] = v;
        }
    }

    // ---------------- phase 2: GEMM (K-tiles 0..8) ----------------
    float c[2][8][4];
    #pragma unroll
    for (int mt = 0; mt < 2; mt++)
        #pragma unroll
        for (int nt = 0; nt < 8; nt++)
            #pragma unroll
            for (int i = 0; i < 4; i++) c[mt][nt][i] = 0.f;

    for (int t = 0; t < 9; t++) {
        if (t + 1 < 9) cp_wait<1>(); else cp_wait<0>();
        __syncthreads();                    // (t==0 also publishes aggregation stores)
        if (t + 2 < 9) issue_tile(t + 2, (t + 2) % 3);

        const uint32_t* as;
        int astr, abase;
        if (t < 4)       { as = aggA;        astr = 68; abase = 16 * t; }
        else if (t == 4) { as = eaggS;       astr = 20; abase = 0; }
        else             { as = axS(t % 3);  astr = 20; abase = 0; }
        const uint32_t* bs = wS(t % 3);

        #pragma unroll
        for (int ks = 0; ks < 2; ks++) {
            const int kw = abase + ks * 8;
            const int kwb = ks * 8;
            uint32_t a[2][4];
            #pragma unroll
            for (int mt = 0; mt < 2; mt++) {
                int row = warp_m * 32 + mt * 16 + gid;
                a[mt][0] = as[row * astr + kw + qid];
                a[mt][1] = as[(row + 8) * astr + kw + qid];
                a[mt][2] = as[row * astr + kw + qid + 4];
                a[mt][3] = as[(row + 8) * astr + kw + qid + 4];
            }
            #pragma unroll
            for (int nt = 0; nt < 8; nt++) {
                int n = warp_n * 64 + nt * 8 + gid;
                uint32_t b0 = bs[n * 20 + kwb + qid];
                uint32_t b1 = bs[n * 20 + kwb + qid + 4];
                mma_f16(c[0][nt], a[0], b0, b1);
                mma_f16(c[1][nt], a[1], b0, b1);
            }
        }
        if (t + 1 < 9) __syncthreads();     // protect stage reuse
    }

    // epilogue (relu always on for layers)
    #pragma unroll
    for (int mt = 0; mt < 2; mt++) {
        int rbase = m0 + warp_m * 32 + mt * 16 + gid;
        #pragma unroll
        for (int h = 0; h < 2; h++) {
            int r = rbase + h * 8;
            if (r >= Nn) continue;
            float coef = degc[r];
            #pragma unroll
            for (int nt = 0; nt < 8; nt++) {
                int j = warp_n * 64 + nt * 8 + qid * 2;
                float v0 = c[mt][nt][h * 2 + 0] + bv0[j]     + coef * bv1[j];
                float v1 = c[mt][nt][h * 2 + 1] + bv0[j + 1] + coef * bv1[j + 1];
                v0 = fmaxf(v0, 0.f); v1 = fmaxf(v1, 0.f);
                __half2 p = __floats2half2_rn(v0, v1);
                *(__half2*)&Ch[(size_t)r * 128 + j] = p;
            }
        }
    }
}

// ---------------------------------------------------------------------------
// fp16 GEMM for the edge predictor (K=128, 4 tiles), 3-stage pipeline.
// blockIdx.y selects (Wpt a -> af with bias) or (Wpt b -> bf).
// ---------------------------------------------------------------------------
#define GEMM_SMEM (3 * 2 * 128 * 20 * 4)

__global__ __launch_bounds__(256)
void k_gemm_pred(const __half* __restrict__ A1,
                 const __half* __restrict__ Wta,
                 const __half* __restrict__ Wtb,
                 const float* __restrict__ bp1,
                 float* __restrict__ Cfa,
                 float* __restrict__ Cfb,
                 int M) {
    extern __shared__ __align__(16) uint32_t smem[];
    auto As = [&](int s) { return smem + s * 5120; };
    auto Bs = [&](int s) { return smem + s * 5120 + 2560; };

    const __half* Wt = (blockIdx.y == 0) ? Wta : Wtb;
    float* Cf        = (blockIdx.y == 0) ? Cfa : Cfb;
    const float* bv0 = (blockIdx.y == 0) ? bp1 : nullptr;

    const int tid    = threadIdx.x;
    const int lane   = tid & 31;
    const int warp   = tid >> 5;
    const int gid    = lane >> 2;
    const int qid    = lane & 3;
    const int warp_m = warp >> 1;
    const int warp_n = warp & 1;
    const int m0     = blockIdx.x * 128;

    float c[2][8][4];
    #pragma unroll
    for (int mt = 0; mt < 2; mt++)
        #pragma unroll
        for (int nt = 0; nt < 8; nt++)
            #pragma unroll
            for (int i = 0; i < 4; i++) c[mt][nt][i] = 0.f;

    auto issue_tile = [&](int t, int s) {
        uint32_t abase = (uint32_t)__cvta_generic_to_shared(As(s));
        uint32_t bbase = (uint32_t)__cvta_generic_to_shared(Bs(s));
        const int kb = t * 32;
        #pragma unroll
        for (int i = 0; i < 2; i++) {
            int chunk = tid + i * 256;
            int r = chunk >> 2, qc = chunk & 3;
            int gm = m0 + r;
            cp16(abase + (r * 20 + qc * 4) * 4,
                 A1 + (size_t)gm * 128 + kb + qc * 8, gm < M ? 16 : 0);
        }
        #pragma unroll
        for (int i = 0; i < 2; i++) {
            int chunk = tid + i * 256;
            int r = chunk >> 2, qc = chunk & 3;
            cp16(bbase + (r * 20 + qc * 4) * 4,
                 Wt + (size_t)r * 128 + kb + qc * 8, 16);
        }
        cp_commit();
    };

    issue_tile(0, 0);
    issue_tile(1, 1);

    for (int t = 0; t < 4; t++) {
        if (t + 1 < 4) cp_wait<1>(); else cp_wait<0>();
        __syncthreads();
        if (t + 2 < 4) issue_tile(t + 2, (t + 2) % 3);

        const uint32_t* as = As(t % 3);
        const uint32_t* bs = Bs(t % 3);
        #pragma unroll
        for (int ks = 0; ks < 2; ks++) {
            const int kw = ks * 8;
            uint32_t a[2][4];
            #pragma unroll
            for (int mt = 0; mt < 2; mt++) {
                int row = warp_m * 32 + mt * 16 + gid;
                a[mt][0] = as[row * 20 + kw + qid];
                a[mt][1] = as[(row + 8) * 20 + kw + qid];
                a[mt][2] = as[row * 20 + kw + qid + 4];
                a[mt][3] = as[(row + 8) * 20 + kw + qid + 4];
            }
            #pragma unroll
            for (int nt = 0; nt < 8; nt++) {
                int n = warp_n * 64 + nt * 8 + gid;
                uint32_t b0 = bs[n * 20 + kw + qid];
                uint32_t b1 = bs[n * 20 + kw + qid + 4];
                mma_f16(c[0][nt], a[0], b0, b1);
                mma_f16(c[1][nt], a[1], b0, b1);
            }
        }
        if (t + 1 < 4) __syncthreads();
    }

    #pragma unroll
    for (int mt = 0; mt < 2; mt++) {
        int rbase = m0 + warp_m * 32 + mt * 16 + gid;
        #pragma unroll
        for (int h = 0; h < 2; h++) {
            int r = rbase + h * 8;
            if (r >= M) continue;
            #pragma unroll
            for (int nt = 0; nt < 8; nt++) {
                int j = warp_n * 64 + nt * 8 + qid * 2;
                float v0 = c[mt][nt][h * 2 + 0];
                float v1 = c[mt][nt][h * 2 + 1];
                if (bv0) { v0 += bv0[j]; v1 += bv0[j + 1]; }
                *(float2*)&Cf[(size_t)r * 128 + j] = make_float2(v0, v1);
            }
        }
    }
}

// ---------------------------------------------------------------------------
// Final edge predictor: out[e] = relu(a[src] + b[dst]) @ Wp2 + bp2
// 4 edges per warp, 8 lanes per edge.
// ---------------------------------------------------------------------------
__global__ void k_edge_final(const float* __restrict__ a,
                             const float* __restrict__ b,
                             const int* __restrict__ ei,
                             const float* __restrict__ Wp2,
                             const float* __restrict__ bp2,
                             float* __restrict__ out,
                             int E, int N) {
    int lane = threadIdx.x & 31;
    int q    = lane & 7;
    int sub  = lane >> 3;
    int warp = (blockIdx.x * blockDim.x + threadIdx.x) >> 5;
    int nwarp = (gridDim.x * blockDim.x) >> 5;

    float4 wA[4], wB[4];
    #pragma unroll
    for (int i = 0; i < 4; i++) {
        int c = q * 4 + i;
        wA[i] = ((const float4*)Wp2)[c * 2];
        wB[i] = ((const float4*)Wp2)[c * 2 + 1];
    }
    float b0 = bp2[0], b1 = bp2[1];

    const float4* a4 = (const float4*)a;
    const float4* b4 = (const float4*)b;

    for (int base = warp * 4; base < E; base += nwarp * 4) {
        int e = base + sub;
        bool valid = (e < E);
        float o0 = 0.f, o1 = 0.f;
        if (valid) {
            int s = ei[e];
            int d = ei[E + e];
            if ((unsigned)s < (unsigned)N && (unsigned)d < (unsigned)N) {
                float4 av[4], bv[4];
                #pragma unroll
                for (int i = 0; i < 4; i++) {
                    av[i] = __ldg(a4 + (size_t)s * 32 + q * 4 + i);
                    bv[i] = __ldg(b4 + (size_t)d * 32 + q * 4 + i);
                }
                #pragma unroll
                for (int i = 0; i < 4; i++) {
                    float z0 = fmaxf(av[i].x + bv[i].x, 0.f);
                    float z1 = fmaxf(av[i].y + bv[i].y, 0.f);
                    float z2 = fmaxf(av[i].z + bv[i].z, 0.f);
                    float z3 = fmaxf(av[i].w + bv[i].w, 0.f);
                    o0 += z0 * wA[i].x + z1 * wA[i].z + z2 * wB[i].x + z3 * wB[i].z;
                    o1 += z0 * wA[i].y + z1 * wA[i].w + z2 * wB[i].y + z3 * wB[i].w;
                }
            } else {
                valid = false;
            }
        }
        #pragma unroll
        for (int off = 4; off > 0; off >>= 1) {
            o0 += __shfl_xor_sync(0xffffffffu, o0, off);
            o1 += __shfl_xor_sync(0xffffffffu, o1, off);
        }
        if (q == 0 && valid) {
            *(float2*)&out[(size_t)e * 2] = make_float2(o0 + b0, o1 + b1);
        }
    }
}

// ---------------------------------------------------------------------------
extern "C" void kernel_launch(void* const* d_in, const int* in_sizes, int n_in,
                              void* d_out, int out_size) {
    const float* x    = (const float*)d_in[0];
    const int*   ei   = (const int*)d_in[1];     // int32
    const float* ea   = (const float*)d_in[2];
    const float* We1  = (const float*)d_in[3];
    const float* be1  = (const float*)d_in[4];
    const float* Wl1  = (const float*)d_in[5];
    const float* bl1  = (const float*)d_in[6];
    const float* Wr1  = (const float*)d_in[7];
    const float* br1  = (const float*)d_in[8];
    const float* We2  = (const float*)d_in[9];
    const float* be2  = (const float*)d_in[10];
    const float* Wl2  = (const float*)d_in[11];
    const float* bl2  = (const float*)d_in[12];
    const float* Wr2  = (const float*)d_in[13];
    const float* br2  = (const float*)d_in[14];
    const float* Wp1  = (const float*)d_in[15];
    const float* bp1  = (const float*)d_in[16];
    const float* Wp2  = (const float*)d_in[17];
    const float* bp2  = (const float*)d_in[18];
    float*       out  = (float*)d_out;

    const int N = in_sizes[0] / 128;
    const int E = in_sizes[2] / 32;

    __half *eaggh, *xh, *h1h, *h2h, *Wcath, *Wpth;
    float *af, *bf, *degc, *bv1, *bv0;
    int *rowptr, *cnt, *bsum, *boff, *csr_src, *csr_eid;
    cudaGetSymbolAddress((void**)&eaggh, g_eaggh);
    cudaGetSymbolAddress((void**)&xh,    g_xh);
    cudaGetSymbolAddress((void**)&h1h,   g_h1h);
    cudaGetSymbolAddress((void**)&h2h,   g_h2h);
    cudaGetSymbolAddress((void**)&af,    g_af);
    cudaGetSymbolAddress((void**)&bf,    g_bf);
    cudaGetSymbolAddress((void**)&degc,  g_degc);
    cudaGetSymbolAddress((void**)&Wcath, g_Wcath);
    cudaGetSymbolAddress((void**)&Wpth,  g_Wpth);
    cudaGetSymbolAddress((void**)&bv1,   g_bv1);
    cudaGetSymbolAddress((void**)&bv0,   g_bv0);
    cudaGetSymbolAddress((void**)&rowptr, g_rowptr);
    cudaGetSymbolAddress((void**)&cnt,    g_cnt);
    cudaGetSymbolAddress((void**)&bsum,   g_bsum);
    cudaGetSymbolAddress((void**)&boff,   g_boff);
    cudaGetSymbolAddress((void**)&csr_src, g_csr_src);
    cudaGetSymbolAddress((void**)&csr_eid, g_csr_eid);

    const int nb    = (N + 511) / 512;
    const int egrid = 2368;
    dim3 ggrid1((N + 127) / 128, 1);
    dim3 ggrid2((N + 127) / 128, 2);

    static int init_done = 0;
    if (!init_done) {
        cudaFuncSetAttribute(k_sage, cudaFuncAttributeMaxDynamicSharedMemorySize, SAGE_SMEM);
        cudaFuncSetAttribute(k_gemm_pred, cudaFuncAttributeMaxDynamicSharedMemorySize, GEMM_SMEM);
        init_done = 1;
    }

    // weight prep + half(x) first (independent of CSR)
    k_wprep<<<3, 128>>>(We1, be1, Wl1, bl1, br1, Wr1,
                        We2, be2, Wl2, bl2, br2, Wr2, Wp1,
                        Wcath, Wpth, bv1, bv0);
    k_xhalf<<<1184, 256>>>((const float4*)x, (uint2*)xh, N * 32);

    // ---- CSR build ----
    cudaMemsetAsync(cnt, 0, (size_t)N * sizeof(int));
    k_hist<<<(E + 255) / 256, 256>>>(ei, cnt, E, N);
    k_scan1<<<nb, 512>>>(cnt, rowptr, bsum, N);
    k_scan2<<<1, 1024>>>(bsum, boff, nb);
    k_scan3<<<nb, 512>>>(rowptr, boff, cnt, degc, N);
    k_fill<<<(E + 255) / 256, 256>>>(ei, rowptr, cnt, csr_src, csr_eid, E, N);

    // ---- fused layers ----
    k_sage<<<ggrid1, 256, SAGE_SMEM>>>(xh, ea, rowptr, csr_src, csr_eid,
                                       Wcath, eaggh, bv0, bv1, degc, h1h, N);
    k_sage<<<ggrid1, 256, SAGE_SMEM>>>(h1h, nullptr, rowptr, csr_src, csr_eid,
                                       Wcath + 128 * 288, eaggh,
                                       bv0 + 128, bv1 + 128, degc, h2h, N);

    // ---- edge predictor (factored; a and b fused via gridDim.y) ----
    k_gemm_pred<<<ggrid2, 256, GEMM_SMEM>>>(h2h, Wpth, Wpth + 128 * 128,
                                            bp1, af, bf, N);

    k_edge_final<<<egrid, 256>>>(af, bf, ei, Wp2, bp2, out, E, N);
}

// round 17
// speedup vs baseline: 1.2582x; 1.2582x over previous
#include <cuda_runtime.h>
#include <cuda_fp16.h>
#include <cstdint>

#define N_NODES_MAX 100000
#define N_EDGES_MAX 600000

// ---------------------------------------------------------------------------
// Scratch (device globals)
// ---------------------------------------------------------------------------
__device__ __align__(16) __half g_aggh [(size_t)N_NODES_MAX * 128];  // mean agg (half)
__device__ __align__(16) __half g_eaggh[(size_t)N_NODES_MAX * 32];   // mean edge_attr (half)
__device__ __align__(16) __half g_xh   [(size_t)N_NODES_MAX * 128];  // half(x)
__device__ __align__(16) __half g_h1h  [(size_t)N_NODES_MAX * 128];  // layer-1 out (half)
__device__ __align__(16) __half g_h2h  [(size_t)N_NODES_MAX * 128];  // layer-2 out (half)
__device__ __align__(16) float  g_af   [(size_t)N_NODES_MAX * 128];  // predictor 'a' (fp32)
__device__ __align__(16) float  g_bf   [(size_t)N_NODES_MAX * 128];  // predictor 'b' (fp32)
__device__ __align__(16) float  g_degc [N_NODES_MAX];                // deg>0 ? 1 : 0
__device__ __align__(16) __half g_Wcath[2 * 128 * 288];              // [n][Wl^T|P^T|Wr^T]
__device__ __align__(16) __half g_Wpth [2 * 128 * 128];              // Wp1a^T, Wp1b^T
__device__ __align__(16) float  g_bv1  [2 * 128];                    // be_l @ Wl_l
__device__ __align__(16) float  g_bv0  [2 * 128];                    // bl_l + br_l
// CSR
__device__ int g_rowptr[N_NODES_MAX + 1];
__device__ int g_cnt   [N_NODES_MAX];
__device__ int g_bsum  [1024];
__device__ int g_boff  [1024];
__device__ int g_csr_src[N_EDGES_MAX];
__device__ int g_csr_eid[N_EDGES_MAX];

// ---------------------------------------------------------------------------
// helpers
// ---------------------------------------------------------------------------
__device__ __forceinline__ void cp16(uint32_t dst, const void* src, int srcsize) {
    asm volatile("cp.async.ca.shared.global [%0], [%1], 16, %2;"
                 :: "r"(dst), "l"(src), "r"(srcsize) : "memory");
}
__device__ __forceinline__ void cp_commit() {
    asm volatile("cp.async.commit_group;" ::: "memory");
}
template <int N>
__device__ __forceinline__ void cp_wait() {
    asm volatile("cp.async.wait_group %0;" :: "n"(N) : "memory");
}
__device__ __forceinline__ void mma_f16(float c[4], const uint32_t a[4],
                                        uint32_t b0, uint32_t b1) {
    asm("mma.sync.aligned.m16n8k16.row.col.f32.f16.f16.f32 "
        "{%0,%1,%2,%3}, {%4,%5,%6,%7}, {%8,%9}, {%0,%1,%2,%3};"
        : "+f"(c[0]), "+f"(c[1]), "+f"(c[2]), "+f"(c[3])
        : "r"(a[0]), "r"(a[1]), "r"(a[2]), "r"(a[3]), "r"(b0), "r"(b1));
}

// ---------------------------------------------------------------------------
// CSR build
// ---------------------------------------------------------------------------
__global__ void k_hist(const int* __restrict__ ei, int* __restrict__ cnt, int E, int N) {
    int e = blockIdx.x * blockDim.x + threadIdx.x;
    if (e < E) {
        int d = ei[E + e];
        if ((unsigned)d < (unsigned)N) atomicAdd(&cnt[d], 1);
    }
}
__global__ void k_scan1(const int* __restrict__ cnt, int* __restrict__ rowptr,
                        int* __restrict__ bsum, int N) {
    __shared__ int sm[512];
    int t = threadIdx.x, b = blockIdx.x, i = b * 512 + t;
    int v = (i < N) ? cnt[i] : 0;
    sm[t] = v;
    __syncthreads();
    #pragma unroll
    for (int off = 1; off < 512; off <<= 1) {
        int add = (t >= off) ? sm[t - off] : 0;
        __syncthreads();
        sm[t] += add;
        __syncthreads();
    }
    if (i < N) rowptr[i + 1] = sm[t];
    if (t == 511) bsum[b] = sm[511];
}
__global__ void k_scan2(const int* __restrict__ bsum, int* __restrict__ boff, int nb) {
    __shared__ int sm[1024];
    int t = threadIdx.x;
    sm[t] = (t < nb) ? bsum[t] : 0;
    __syncthreads();
    #pragma unroll
    for (int off = 1; off < 1024; off <<= 1) {
        int add = (t >= off) ? sm[t - off] : 0;
        __syncthreads();
        sm[t] += add;
        __syncthreads();
    }
    if (t < nb) boff[t] = (t == 0) ? 0 : sm[t - 1];
}
__global__ void k_scan3(int* __restrict__ rowptr, const int* __restrict__ boff,
                        int* __restrict__ cnt, float* __restrict__ degc, int N) {
    int t = threadIdx.x, b = blockIdx.x, i = b * 512 + t;
    if (i < N) {
        rowptr[i + 1] += boff[b];
        degc[i] = cnt[i] > 0 ? 1.f : 0.f;
        cnt[i] = 0;
        if (i == 0) rowptr[0] = 0;
    }
}
__global__ void k_fill(const int* __restrict__ ei, const int* __restrict__ rowptr,
                       int* __restrict__ cnt, int* __restrict__ csr_src,
                       int* __restrict__ csr_eid, int E, int N) {
    int e = blockIdx.x * blockDim.x + threadIdx.x;
    if (e < E) {
        int s = ei[e];
        int d = ei[E + e];
        if ((unsigned)d < (unsigned)N) {
            int pos = rowptr[d] + atomicAdd(&cnt[d], 1);
            csr_src[pos] = s;
            csr_eid[pos] = e;
        }
    }
}

// ---------------------------------------------------------------------------
// x -> half copy
// ---------------------------------------------------------------------------
__global__ void k_xhalf(const float4* __restrict__ x, uint2* __restrict__ xh, int n4) {
    int i = blockIdx.x * blockDim.x + threadIdx.x;
    int stride = gridDim.x * blockDim.x;
    for (; i < n4; i += stride) {
        float4 v = x[i];
        __half2 p0 = __floats2half2_rn(v.x, v.y);
        __half2 p1 = __floats2half2_rn(v.z, v.w);
        uint2 u;
        u.x = *(uint32_t*)&p0;
        u.y = *(uint32_t*)&p1;
        xh[i] = u;
    }
}

// ---------------------------------------------------------------------------
// CSR aggregation: one warp per node, fp32 accumulate, MEAN written as half.
// ---------------------------------------------------------------------------
__global__ void k_agg_l1(const __half* __restrict__ xh, const float* __restrict__ ea,
                         const int* __restrict__ rowptr,
                         const int* __restrict__ csr_src, const int* __restrict__ csr_eid,
                         __half* __restrict__ aggh, __half* __restrict__ eaggh, int N) {
    int lane = threadIdx.x & 31;
    int n = (blockIdx.x * blockDim.x + threadIdx.x) >> 5;
    if (n >= N) return;
    int beg = rowptr[n], end = rowptr[n + 1];
    float inv = 1.f / fmaxf((float)(end - beg), 1.f);
    const uint2* x2 = (const uint2*)xh;
    float4 acc = make_float4(0.f, 0.f, 0.f, 0.f);
    float eacc = 0.f;
    int i = beg;
    for (; i + 1 < end; i += 2) {
        int s0 = __ldg(&csr_src[i]),     e0 = __ldg(&csr_eid[i]);
        int s1 = __ldg(&csr_src[i + 1]), e1 = __ldg(&csr_eid[i + 1]);
        uint2 u0 = __ldg(x2 + (size_t)s0 * 32 + lane);
        uint2 u1 = __ldg(x2 + (size_t)s1 * 32 + lane);
        float w0 = __ldg(&ea[(size_t)e0 * 32 + lane]);
        float w1 = __ldg(&ea[(size_t)e1 * 32 + lane]);
        float2 a0 = __half22float2(*(__half2*)&u0.x);
        float2 a1 = __half22float2(*(__half2*)&u0.y);
        float2 b0 = __half22float2(*(__half2*)&u1.x);
        float2 b1 = __half22float2(*(__half2*)&u1.y);
        acc.x += a0.x + b0.x; acc.y += a0.y + b0.y;
        acc.z += a1.x + b1.x; acc.w += a1.y + b1.y;
        eacc += w0 + w1;
    }
    if (i < end) {
        int s0 = __ldg(&csr_src[i]), e0 = __ldg(&csr_eid[i]);
        uint2 u0 = __ldg(x2 + (size_t)s0 * 32 + lane);
        float w0 = __ldg(&ea[(size_t)e0 * 32 + lane]);
        float2 a0 = __half22float2(*(__half2*)&u0.x);
        float2 a1 = __half22float2(*(__half2*)&u0.y);
        acc.x += a0.x; acc.y += a0.y; acc.z += a1.x; acc.w += a1.y;
        eacc += w0;
    }
    __half2 p0 = __floats2half2_rn(acc.x * inv, acc.y * inv);
    __half2 p1 = __floats2half2_rn(acc.z * inv, acc.w * inv);
    uint2 u;
    u.x = *(uint32_t*)&p0;
    u.y = *(uint32_t*)&p1;
    ((uint2*)aggh)[(size_t)n * 32 + lane] = u;
    eaggh[(size_t)n * 32 + lane] = __float2half_rn(eacc * inv);
}

__global__ void k_agg_l2(const __half* __restrict__ xh,
                         const int* __restrict__ rowptr,
                         const int* __restrict__ csr_src,
                         __half* __restrict__ aggh, int N) {
    int lane = threadIdx.x & 31;
    int n = (blockIdx.x * blockDim.x + threadIdx.x) >> 5;
    if (n >= N) return;
    int beg = rowptr[n], end = rowptr[n + 1];
    float inv = 1.f / fmaxf((float)(end - beg), 1.f);
    const uint2* x2 = (const uint2*)xh;
    float4 acc = make_float4(0.f, 0.f, 0.f, 0.f);
    for (int i = beg; i < end; i++) {
        int s0 = __ldg(&csr_src[i]);
        uint2 u = __ldg(x2 + (size_t)s0 * 32 + lane);
        float2 f0 = __half22float2(*(__half2*)&u.x);
        float2 f1 = __half22float2(*(__half2*)&u.y);
        acc.x += f0.x; acc.y += f0.y; acc.z += f1.x; acc.w += f1.y;
    }
    __half2 p0 = __floats2half2_rn(acc.x * inv, acc.y * inv);
    __half2 p1 = __floats2half2_rn(acc.z * inv, acc.w * inv);
    uint2 u;
    u.x = *(uint32_t*)&p0;
    u.y = *(uint32_t*)&p1;
    ((uint2*)aggh)[(size_t)n * 32 + lane] = u;
}

// ---------------------------------------------------------------------------
// Weight prep (half, transposed K-major)
// ---------------------------------------------------------------------------
__global__ void k_wprep(const float* We1, const float* be1, const float* Wl1,
                        const float* bl1, const float* br1, const float* Wr1,
                        const float* We2, const float* be2, const float* Wl2,
                        const float* bl2, const float* br2, const float* Wr2,
                        const float* Wp1,
                        __half* Wcat, __half* Wpt, float* bv1, float* bv0) {
    int l = blockIdx.x;
    int j = threadIdx.x;
    if (l < 2) {
        const float* We = l ? We2 : We1;
        const float* be = l ? be2 : be1;
        const float* Wl = l ? Wl2 : Wl1;
        const float* bl = l ? bl2 : bl1;
        const float* br = l ? br2 : br1;
        const float* Wr = l ? Wr2 : Wr1;
        __half* row = Wcat + (size_t)l * 128 * 288 + (size_t)j * 288;
        for (int k = 0; k < 128; k++) row[k] = __float2half_rn(Wl[k * 128 + j]);
        for (int i = 0; i < 32; i++) {
            float acc = 0.f;
            for (int k = 0; k < 128; k++) acc = fmaf(We[i * 128 + k], Wl[k * 128 + j], acc);
            row[128 + i] = __float2half_rn(acc);
        }
        for (int k = 0; k < 128; k++) row[160 + k] = __float2half_rn(Wr[k * 128 + j]);
        float a1 = 0.f;
        for (int k = 0; k < 128; k++) a1 = fmaf(be[k], Wl[k * 128 + j], a1);
        bv1[l * 128 + j] = a1;
        bv0[l * 128 + j] = bl[j] + br[j];
    } else {
        __half* ra = Wpt + (size_t)j * 128;
        __half* rb = Wpt + (size_t)128 * 128 + (size_t)j * 128;
        for (int k = 0; k < 128; k++) {
            ra[k] = __float2half_rn(Wp1[k * 128 + j]);
            rb[k] = __float2half_rn(Wp1[(128 + k) * 128 + j]);
        }
    }
}

// ---------------------------------------------------------------------------
// fp16 tensor-core SAGE GEMM (mma.sync m16n8k16), cp.async double-buffered.
//   C = act( A1 @ W^T + (A2 @ P^T)? + (B @ Wr^T)? + bv0? + degc[m]*bv1? )
// BM=128, BN=128, BK=32 halves. 256 threads = 8 warps 4x2; warp = 32x64.
// smem rows padded to 20 words: frag banks (20g+q)%32 all distinct.
// blockIdx.y==1 selects alternate problem (Wt2, bv0=null, Cf2) — predictor b.
// ---------------------------------------------------------------------------
__global__ __launch_bounds__(256)
void k_gemm_f16(const __half* __restrict__ A1,
                const __half* __restrict__ A2,
                const __half* __restrict__ B,
                const __half* __restrict__ Wt, int wstride, int ktiles,
                const float* __restrict__ bv0,
                const float* __restrict__ bv1,
                const float* __restrict__ degc,
                __half* __restrict__ Ch,
                float* __restrict__ Cf,
                const __half* __restrict__ Wt2,
                float* __restrict__ Cf2,
                int M, int relu) {
    __shared__ __align__(16) uint32_t As[2][128][20];
    __shared__ __align__(16) uint32_t Bs[2][128][20];

    if (blockIdx.y == 1) { Wt = Wt2; Cf = Cf2; bv0 = nullptr; }

    const int tid    = threadIdx.x;
    const int lane   = tid & 31;
    const int warp   = tid >> 5;
    const int gid    = lane >> 2;
    const int qid    = lane & 3;
    const int warp_m = warp >> 1;
    const int warp_n = warp & 1;
    const int m0     = blockIdx.x * 128;

    float c[2][8][4];
    #pragma unroll
    for (int mt = 0; mt < 2; mt++)
        #pragma unroll
        for (int nt = 0; nt < 8; nt++)
            #pragma unroll
            for (int i = 0; i < 4; i++) c[mt][nt][i] = 0.f;

    // 512 16B-chunks per tile (A:512, B:512) -> 2 iters x 256 threads each
    auto issue_tile = [&](int t, int buf) {
        const __half* Ap;
        int astr, akb;
        if (ktiles == 4 || t < 4) { Ap = A1; astr = 128; akb = t * 32; }
        else if (t == 4)          { Ap = A2; astr = 32;  akb = 0;      }
        else                      { Ap = B;  astr = 128; akb = (t - 5) * 32; }
        const int bkb = t * 32;
        #pragma unroll
        for (int i = 0; i < 2; i++) {
            int chunk = tid + i * 256;      // 0..511
            int r = chunk >> 2, qc = chunk & 3;
            int gm = m0 + r;
            uint32_t dst = (uint32_t)__cvta_generic_to_shared(&As[buf][r][qc * 4]);
            cp16(dst, Ap + (size_t)gm * astr + akb + qc * 8, gm < M ? 16 : 0);
        }
        #pragma unroll
        for (int i = 0; i < 2; i++) {
            int chunk = tid + i * 256;      // 0..511
            int r = chunk >> 2, qc = chunk & 3;
            uint32_t dst = (uint32_t)__cvta_generic_to_shared(&Bs[buf][r][qc * 4]);
            cp16(dst, Wt + (size_t)r * wstride + bkb + qc * 8, 16);
        }
        cp_commit();
    };

    issue_tile(0, 0);
    int buf = 0;

    for (int t = 0; t < ktiles; t++) {
        const bool has_next = (t + 1 < ktiles);
        if (has_next) issue_tile(t + 1, buf ^ 1);
        if (has_next) cp_wait<1>(); else cp_wait<0>();
        __syncthreads();

        #pragma unroll
        for (int ks = 0; ks < 2; ks++) {
            const int kw = ks * 8;
            uint32_t a[2][4];
            #pragma unroll
            for (int mt = 0; mt < 2; mt++) {
                int row = warp_m * 32 + mt * 16 + gid;
                a[mt][0] = As[buf][row][kw + qid];
                a[mt][1] = As[buf][row + 8][kw + qid];
                a[mt][2] = As[buf][row][kw + qid + 4];
                a[mt][3] = As[buf][row + 8][kw + qid + 4];
            }
            #pragma unroll
            for (int nt = 0; nt < 8; nt++) {
                int n = warp_n * 64 + nt * 8 + gid;
                uint32_t b0 = Bs[buf][n][kw + qid];
                uint32_t b1 = Bs[buf][n][kw + qid + 4];
                mma_f16(c[0][nt], a[0], b0, b1);
                mma_f16(c[1][nt], a[1], b0, b1);
            }
        }
        __syncthreads();
        buf ^= 1;
    }

    // epilogue
    #pragma unroll
    for (int mt = 0; mt < 2; mt++) {
        int rbase = m0 + warp_m * 32 + mt * 16 + gid;
        #pragma unroll
        for (int h = 0; h < 2; h++) {
            int r = rbase + h * 8;
            if (r >= M) continue;
            float coef = (bv1 && degc) ? degc[r] : 0.f;
            #pragma unroll
            for (int nt = 0; nt < 8; nt++) {
                int j = warp_n * 64 + nt * 8 + qid * 2;
                float v0 = c[mt][nt][h * 2 + 0];
                float v1 = c[mt][nt][h * 2 + 1];
                if (bv0) { v0 += bv0[j]; v1 += bv0[j + 1]; }
                if (bv1) { v0 += coef * bv1[j]; v1 += coef * bv1[j + 1]; }
                if (relu) { v0 = fmaxf(v0, 0.f); v1 = fmaxf(v1, 0.f); }
                if (Ch) {
                    __half2 p = __floats2half2_rn(v0, v1);
                    *(__half2*)&Ch[(size_t)r * 128 + j] = p;
                } else {
                    *(float2*)&Cf[(size_t)r * 128 + j] = make_float2(v0, v1);
                }
            }
        }
    }
}

// ---------------------------------------------------------------------------
// Final edge predictor: out[e] = relu(a[src] + b[dst]) @ Wp2 + bp2
// 4 edges per warp, 8 lanes per edge (lane owns 16 features).
// ---------------------------------------------------------------------------
__global__ void k_edge_final(const float* __restrict__ a,
                             const float* __restrict__ b,
                             const int* __restrict__ ei,
                             const float* __restrict__ Wp2,
                             const float* __restrict__ bp2,
                             float* __restrict__ out,
                             int E, int N) {
    int lane = threadIdx.x & 31;
    int q    = lane & 7;
    int sub  = lane >> 3;
    int warp = (blockIdx.x * blockDim.x + threadIdx.x) >> 5;
    int nwarp = (gridDim.x * blockDim.x) >> 5;

    float4 wA[4], wB[4];
    #pragma unroll
    for (int i = 0; i < 4; i++) {
        int c = q * 4 + i;
        wA[i] = ((const float4*)Wp2)[c * 2];
        wB[i] = ((const float4*)Wp2)[c * 2 + 1];
    }
    float b0 = bp2[0], b1 = bp2[1];

    const float4* a4 = (const float4*)a;
    const float4* b4 = (const float4*)b;

    for (int base = warp * 4; base < E; base += nwarp * 4) {
        int e = base + sub;
        bool valid = (e < E);
        float o0 = 0.f, o1 = 0.f;
        if (valid) {
            int s = ei[e];
            int d = ei[E + e];
            if ((unsigned)s < (unsigned)N && (unsigned)d < (unsigned)N) {
                float4 av[4], bv[4];
                #pragma unroll
                for (int i = 0; i < 4; i++) {
                    av[i] = __ldg(a4 + (size_t)s * 32 + q * 4 + i);
                    bv[i] = __ldg(b4 + (size_t)d * 32 + q * 4 + i);
                }
                #pragma unroll
                for (int i = 0; i < 4; i++) {
                    float z0 = fmaxf(av[i].x + bv[i].x, 0.f);
                    float z1 = fmaxf(av[i].y + bv[i].y, 0.f);
                    float z2 = fmaxf(av[i].z + bv[i].z, 0.f);
                    float z3 = fmaxf(av[i].w + bv[i].w, 0.f);
                    o0 += z0 * wA[i].x + z1 * wA[i].z + z2 * wB[i].x + z3 * wB[i].z;
                    o1 += z0 * wA[i].y + z1 * wA[i].w + z2 * wB[i].y + z3 * wB[i].w;
                }
            } else {
                valid = false;
            }
        }
        #pragma unroll
        for (int off = 4; off > 0; off >>= 1) {
            o0 += __shfl_xor_sync(0xffffffffu, o0, off);
            o1 += __shfl_xor_sync(0xffffffffu, o1, off);
        }
        if (q == 0 && valid) {
            *(float2*)&out[(size_t)e * 2] = make_float2(o0 + b0, o1 + b1);
        }
    }
}

// ---------------------------------------------------------------------------
extern "C" void kernel_launch(void* const* d_in, const int* in_sizes, int n_in,
                              void* d_out, int out_size) {
    const float* x    = (const float*)d_in[0];
    const int*   ei   = (const int*)d_in[1];     // int32
    const float* ea   = (const float*)d_in[2];
    const float* We1  = (const float*)d_in[3];
    const float* be1  = (const float*)d_in[4];
    const float* Wl1  = (const float*)d_in[5];
    const float* bl1  = (const float*)d_in[6];
    const float* Wr1  = (const float*)d_in[7];
    const float* br1  = (const float*)d_in[8];
    const float* We2  = (const float*)d_in[9];
    const float* be2  = (const float*)d_in[10];
    const float* Wl2  = (const float*)d_in[11];
    const float* bl2  = (const float*)d_in[12];
    const float* Wr2  = (const float*)d_in[13];
    const float* br2  = (const float*)d_in[14];
    const float* Wp1  = (const float*)d_in[15];
    const float* bp1  = (const float*)d_in[16];
    const float* Wp2  = (const float*)d_in[17];
    const float* bp2  = (const float*)d_in[18];
    float*       out  = (float*)d_out;

    const int N = in_sizes[0] / 128;
    const int E = in_sizes[2] / 32;

    __half *aggh, *eaggh, *xh, *h1h, *h2h, *Wcath, *Wpth;
    float *af, *bf, *degc, *bv1, *bv0;
    int *rowptr, *cnt, *bsum, *boff, *csr_src, *csr_eid;
    cudaGetSymbolAddress((void**)&aggh,  g_aggh);
    cudaGetSymbolAddress((void**)&eaggh, g_eaggh);
    cudaGetSymbolAddress((void**)&xh,    g_xh);
    cudaGetSymbolAddress((void**)&h1h,   g_h1h);
    cudaGetSymbolAddress((void**)&h2h,   g_h2h);
    cudaGetSymbolAddress((void**)&af,    g_af);
    cudaGetSymbolAddress((void**)&bf,    g_bf);
    cudaGetSymbolAddress((void**)&degc,  g_degc);
    cudaGetSymbolAddress((void**)&Wcath, g_Wcath);
    cudaGetSymbolAddress((void**)&Wpth,  g_Wpth);
    cudaGetSymbolAddress((void**)&bv1,   g_bv1);
    cudaGetSymbolAddress((void**)&bv0,   g_bv0);
    cudaGetSymbolAddress((void**)&rowptr, g_rowptr);
    cudaGetSymbolAddress((void**)&cnt,    g_cnt);
    cudaGetSymbolAddress((void**)&bsum,   g_bsum);
    cudaGetSymbolAddress((void**)&boff,   g_boff);
    cudaGetSymbolAddress((void**)&csr_src, g_csr_src);
    cudaGetSymbolAddress((void**)&csr_eid, g_csr_eid);

    const int nb    = (N + 511) / 512;
    const int agrid = (N + 7) / 8;
    const int egrid = 2368;
    dim3 ggrid1((N + 127) / 128, 1);
    dim3 ggrid2((N + 127) / 128, 2);

    // side stream + fork/join events (created once, on the uncaptured first call)
    static cudaStream_t s2 = nullptr;
    static cudaEvent_t ev_fork = nullptr, ev_join = nullptr;
    if (!s2) {
        cudaStreamCreateWithFlags(&s2, cudaStreamNonBlocking);
        cudaEventCreateWithFlags(&ev_fork, cudaEventDisableTiming);
        cudaEventCreateWithFlags(&ev_join, cudaEventDisableTiming);
    }

    // ---- fork: weight prep + half(x) on side stream, CSR build on main ----
    cudaEventRecord(ev_fork, 0);
    cudaStreamWaitEvent(s2, ev_fork, 0);
    k_wprep<<<3, 128, 0, s2>>>(We1, be1, Wl1, bl1, br1, Wr1,
                               We2, be2, Wl2, bl2, br2, Wr2, Wp1,
                               Wcath, Wpth, bv1, bv0);
    k_xhalf<<<1184, 256, 0, s2>>>((const float4*)x, (uint2*)xh, N * 32);
    cudaEventRecord(ev_join, s2);

    // ---- CSR build (main stream) ----
    cudaMemsetAsync(cnt, 0, (size_t)N * sizeof(int));
    k_hist<<<(E + 255) / 256, 256>>>(ei, cnt, E, N);
    k_scan1<<<nb, 512>>>(cnt, rowptr, bsum, N);
    k_scan2<<<1, 1024>>>(bsum, boff, nb);
    k_scan3<<<nb, 512>>>(rowptr, boff, cnt, degc, N);
    k_fill<<<(E + 255) / 256, 256>>>(ei, rowptr, cnt, csr_src, csr_eid, E, N);

    // ---- join ----
    cudaStreamWaitEvent(0, ev_join, 0);

    // ---- layer 1 ----
    k_agg_l1<<<agrid, 256>>>(xh, ea, rowptr, csr_src, csr_eid, aggh, eaggh, N);
    k_gemm_f16<<<ggrid1, 256>>>(aggh, eaggh, xh, Wcath, 288, 9,
                                bv0, bv1, degc, h1h, nullptr,
                                nullptr, nullptr, N, 1);

    // ---- layer 2 ----
    k_agg_l2<<<agrid, 256>>>(h1h, rowptr, csr_src, aggh, N);
    k_gemm_f16<<<ggrid1, 256>>>(aggh, eaggh, h1h, Wcath + 128 * 288, 288, 9,
                                bv0 + 128, bv1 + 128, degc, h2h, nullptr,
                                nullptr, nullptr, N, 1);

    // ---- edge predictor (factored, fused a+b via gridDim.y) ----
    k_gemm_f16<<<ggrid2, 256>>>(h2h, nullptr, nullptr, Wpth, 128, 4,
                                bp1, nullptr, nullptr, nullptr, af,
                                Wpth + 128 * 128, bf, N, 0);

    k_edge_final<<<egrid, 256>>>(af, bf, ei, Wp2, bp2, out, E, N);
}